// round 1
// baseline (speedup 1.0000x reference)
#include <cuda_runtime.h>
#include <math.h>

#define HW   (128 * 128)
#define Hh   128
#define Ww   128
#define Bb   4
#define Cc   64
#define Oo   64
#define K2   9

// Scratch for offsets/mask: [B][27][H][W]  (planes: 0..8 dy_k, 9..17 dx_k, 18..26 mask_k)
__device__ float g_scratch[Bb * 27 * HW];

// ---------------------------------------------------------------------------
// Kernel 1: fused offset-conv (18 ch) + modulator-conv (9 ch) + 2*sigmoid.
// One thread per output pixel. Block = 256 threads = 2 rows of 128.
// Weights staged in smem transposed to [k][c][o_pad] so the o-loop is float4.
// Input rows staged per-channel in smem tiles (4 rows x 130 cols, zero-padded).
// ---------------------------------------------------------------------------
#define W2O_STRIDE 20   // 18 out-ch padded to 20 (5 float4)
#define W2M_STRIDE 12   // 9 out-ch padded to 12 (3 float4)
#define TILE_STRIDE 132

__global__ __launch_bounds__(256, 2)
void offmask_kernel(const float* __restrict__ omap, const float* __restrict__ mmap,
                    const float* __restrict__ ow,   const float* __restrict__ obias,
                    const float* __restrict__ mw,   const float* __restrict__ mbias)
{
    extern __shared__ float sm[];
    float* w2o    = sm;                          // [9][64][20] = 11520
    float* w2m    = w2o + 9 * 64 * W2O_STRIDE;   // [9][64][12] = 6912
    float* tile_o = w2m + 9 * 64 * W2M_STRIDE;   // [4][132]    = 528
    float* tile_m = tile_o + 4 * TILE_STRIDE;    // [4][132]    = 528

    const int tid = threadIdx.x;
    const int b   = blockIdx.x >> 6;         // 0..3
    const int by  = blockIdx.x & 63;         // row-pair index 0..63

    // Stage transposed weights: w2o[(k*64+c)*20 + o] = ow[o*576 + c*9 + k]
    for (int i = tid; i < 18 * 64 * 9; i += 256) {
        int o = i / 576; int r = i % 576; int c = r / 9; int k = r % 9;
        w2o[(k * 64 + c) * W2O_STRIDE + o] = ow[i];
    }
    for (int i = tid; i < 9 * 64 * 9; i += 256) {
        int o = i / 576; int r = i % 576; int c = r / 9; int k = r % 9;
        w2m[(k * 64 + c) * W2M_STRIDE + o] = mw[i];
    }
    // Zero the padding lanes
    for (int i = tid; i < 9 * 64; i += 256) {
        w2o[i * W2O_STRIDE + 18] = 0.f; w2o[i * W2O_STRIDE + 19] = 0.f;
        w2m[i * W2M_STRIDE + 9]  = 0.f; w2m[i * W2M_STRIDE + 10] = 0.f;
        w2m[i * W2M_STRIDE + 11] = 0.f;
    }
    __syncthreads();

    const int ly = tid >> 7;       // 0..1
    const int lx = tid & 127;      // 0..127
    const int oy = by * 2 + ly;    // output row

    float4 acco[5];
    float4 accm[3];
#pragma unroll
    for (int j = 0; j < 5; j++) acco[j] = make_float4(0.f, 0.f, 0.f, 0.f);
#pragma unroll
    for (int j = 0; j < 3; j++) accm[j] = make_float4(0.f, 0.f, 0.f, 0.f);

    const float* ob_base = omap + (size_t)b * Cc * HW;
    const float* mb_base = mmap + (size_t)b * Cc * HW;

    for (int c = 0; c < Cc; c++) {
        __syncthreads();
        // Stage 4 input rows (by*2-1 .. by*2+2), cols -1..128, zero padded.
        for (int i = tid; i < 4 * 130; i += 256) {
            int r = i / 130, cc = i % 130;
            int gy = by * 2 - 1 + r, gx = cc - 1;
            bool ok = (gy >= 0) & (gy < Hh) & (gx >= 0) & (gx < Ww);
            int gidx = c * HW + gy * Ww + gx;
            tile_o[r * TILE_STRIDE + cc] = ok ? ob_base[gidx] : 0.f;
            tile_m[r * TILE_STRIDE + cc] = ok ? mb_base[gidx] : 0.f;
        }
        __syncthreads();

        float iv[9], mv[9];
#pragma unroll
        for (int k = 0; k < 9; k++) {
            int idx = (ly + k / 3) * TILE_STRIDE + lx + (k % 3);
            iv[k] = tile_o[idx];
            mv[k] = tile_m[idx];
        }
#pragma unroll
        for (int k = 0; k < 9; k++) {
            const float4* wro = (const float4*)&w2o[(k * 64 + c) * W2O_STRIDE];
            float a = iv[k];
#pragma unroll
            for (int j = 0; j < 5; j++) {
                float4 w = wro[j];
                acco[j].x = fmaf(a, w.x, acco[j].x);
                acco[j].y = fmaf(a, w.y, acco[j].y);
                acco[j].z = fmaf(a, w.z, acco[j].z);
                acco[j].w = fmaf(a, w.w, acco[j].w);
            }
            const float4* wrm = (const float4*)&w2m[(k * 64 + c) * W2M_STRIDE];
            float m = mv[k];
#pragma unroll
            for (int j = 0; j < 3; j++) {
                float4 w = wrm[j];
                accm[j].x = fmaf(m, w.x, accm[j].x);
                accm[j].y = fmaf(m, w.y, accm[j].y);
                accm[j].z = fmaf(m, w.z, accm[j].z);
                accm[j].w = fmaf(m, w.w, accm[j].w);
            }
        }
    }

    // Unpack + bias + write to scratch
    float vo[20], vm[12];
#pragma unroll
    for (int j = 0; j < 5; j++) {
        vo[j*4+0] = acco[j].x; vo[j*4+1] = acco[j].y;
        vo[j*4+2] = acco[j].z; vo[j*4+3] = acco[j].w;
    }
#pragma unroll
    for (int j = 0; j < 3; j++) {
        vm[j*4+0] = accm[j].x; vm[j*4+1] = accm[j].y;
        vm[j*4+2] = accm[j].z; vm[j*4+3] = accm[j].w;
    }
    const int p = oy * Ww + lx;
    float* S = g_scratch + (size_t)b * 27 * HW;
#pragma unroll
    for (int k = 0; k < 9; k++) {
        S[k * HW + p]        = vo[2 * k]     + __ldg(&obias[2 * k]);
        S[(9 + k) * HW + p]  = vo[2 * k + 1] + __ldg(&obias[2 * k + 1]);
        float z = vm[k] + __ldg(&mbias[k]);
        S[(18 + k) * HW + p] = 2.0f / (1.0f + expf(-z));
    }
}

// ---------------------------------------------------------------------------
// Kernel 2: deformable conv main GEMM.
// One thread per output pixel; 64 fp32 accumulators (all output channels).
// Tap descriptors (y0,x0,wy,wx,mask for 9 taps) precomputed in registers.
// Weight chunked over 16 input channels into smem, layout [ck][o] stride 68.
// Bilinear gathers from x go straight to L1/L2 (x is 4 MB; fits in L2).
// ---------------------------------------------------------------------------
#define CCH 16
#define WS_STRIDE 68    // 64 padded to 68 floats (17 float4) to dodge STS bank conflicts

__global__ __launch_bounds__(256, 2)
void deform_kernel(const float* __restrict__ x, const float* __restrict__ weight,
                   float* __restrict__ out)
{
    __shared__ float ws[CCH * 9 * WS_STRIDE];   // 9792 floats = 38.25 KB

    const int tid = threadIdx.x;
    const int b   = blockIdx.x >> 6;
    const int by  = blockIdx.x & 63;
    const int ly  = tid >> 7;
    const int lx  = tid & 127;
    const int ho  = by * 2 + ly;
    const int wo  = lx;
    const int p   = ho * Ww + wo;

    const float* S = g_scratch + (size_t)b * 27 * HW;

    // Tap descriptors
    int   ty0[9], tx0[9];
    float twy[9], twx[9], tm[9];
#pragma unroll
    for (int k = 0; k < 9; k++) {
        float dy = S[k * HW + p];
        float dx = S[(9 + k) * HW + p];
        tm[k]    = S[(18 + k) * HW + p];
        float py = dy + (float)(ho - 1 + k / 3);
        float px = dx + (float)(wo - 1 + k % 3);
        float fy = floorf(py), fx = floorf(px);
        ty0[k] = (int)fy;  tx0[k] = (int)fx;
        twy[k] = py - fy;  twx[k] = px - fx;
    }

    float4 acc[16];
#pragma unroll
    for (int j = 0; j < 16; j++) acc[j] = make_float4(0.f, 0.f, 0.f, 0.f);

    const float* xb = x + (size_t)b * Cc * HW;

    for (int cc = 0; cc < Cc; cc += CCH) {
        __syncthreads();
        // Stage weight chunk transposed: ws[(cl*9+k)*68 + o] = weight[o][cc+cl][k]
        for (int i = tid; i < CCH * 9 * 64; i += 256) {
            int o = i / (CCH * 9); int r = i % (CCH * 9); int cl = r / 9; int k = r % 9;
            ws[(cl * 9 + k) * WS_STRIDE + o] = weight[o * 576 + (cc + cl) * 9 + k];
        }
        __syncthreads();

        for (int cl = 0; cl < CCH; cl++) {
            const float* xc = xb + (cc + cl) * HW;
            float s[9];
#pragma unroll
            for (int k = 0; k < 9; k++) {
                int y0 = ty0[k], x0 = tx0[k];
                int y1 = y0 + 1, x1 = x0 + 1;
                bool yv0 = ((unsigned)y0 < (unsigned)Hh);
                bool yv1 = ((unsigned)y1 < (unsigned)Hh);
                bool xv0 = ((unsigned)x0 < (unsigned)Ww);
                bool xv1 = ((unsigned)x1 < (unsigned)Ww);
                float v00 = (yv0 && xv0) ? __ldg(xc + y0 * Ww + x0) : 0.f;
                float v01 = (yv0 && xv1) ? __ldg(xc + y0 * Ww + x1) : 0.f;
                float v10 = (yv1 && xv0) ? __ldg(xc + y1 * Ww + x0) : 0.f;
                float v11 = (yv1 && xv1) ? __ldg(xc + y1 * Ww + x1) : 0.f;
                float wy = twy[k], wx = twx[k];
                float top = fmaf(v01 - v00, wx, v00);
                float bot = fmaf(v11 - v10, wx, v10);
                s[k] = fmaf(bot - top, wy, top) * tm[k];
            }
            const float* wbase = &ws[(cl * 9) * WS_STRIDE];
#pragma unroll
            for (int j = 0; j < 16; j++) {
                float4 a = acc[j];
#pragma unroll
                for (int k = 0; k < 9; k++) {
                    float4 w = *(const float4*)&wbase[k * WS_STRIDE + j * 4];
                    a.x = fmaf(s[k], w.x, a.x);
                    a.y = fmaf(s[k], w.y, a.y);
                    a.z = fmaf(s[k], w.z, a.z);
                    a.w = fmaf(s[k], w.w, a.w);
                }
                acc[j] = a;
            }
        }
    }

    // Write out: out[b][o][ho][wo], o-strided (each STG coalesced across lanes)
    float* op = out + (size_t)b * Oo * HW + p;
#pragma unroll
    for (int j = 0; j < 16; j++) {
        op[(j * 4 + 0) * HW] = acc[j].x;
        op[(j * 4 + 1) * HW] = acc[j].y;
        op[(j * 4 + 2) * HW] = acc[j].z;
        op[(j * 4 + 3) * HW] = acc[j].w;
    }
}

// ---------------------------------------------------------------------------

extern "C" void kernel_launch(void* const* d_in, const int* in_sizes, int n_in,
                              void* d_out, int out_size)
{
    const float* x     = (const float*)d_in[0];
    const float* omap  = (const float*)d_in[1];
    const float* mmap  = (const float*)d_in[2];
    const float* ow    = (const float*)d_in[3];
    const float* obias = (const float*)d_in[4];
    const float* mw    = (const float*)d_in[5];
    const float* mbias = (const float*)d_in[6];
    const float* w     = (const float*)d_in[7];
    float* out = (float*)d_out;

    const int smem1 = (9 * 64 * W2O_STRIDE + 9 * 64 * W2M_STRIDE + 2 * 4 * TILE_STRIDE)
                      * (int)sizeof(float);   // ~76 KB -> needs opt-in
    cudaFuncSetAttribute(offmask_kernel, cudaFuncAttributeMaxDynamicSharedMemorySize, smem1);

    dim3 grid(Bb * (Hh / 2));   // 256 blocks
    dim3 block(256);

    offmask_kernel<<<grid, block, smem1>>>(omap, mmap, ow, obias, mw, mbias);
    deform_kernel<<<grid, block>>>(x, w, out);
}

// round 2
// speedup vs baseline: 1.3426x; 1.3426x over previous
#include <cuda_runtime.h>
#include <math.h>

#define HW   (128 * 128)
#define Hh   128
#define Ww   128
#define Bb   4
#define Cc   64
#define Oo   64

// Scratch: offsets/mask planes [B][27][H][W]  (0..8 dy_k, 9..17 dx_k, 18..26 mask_k)
__device__ float g_scratch[Bb * 27 * HW];
// Pre-transposed main weight: [k][c][o]  (9*64*64)
__device__ float g_wt[9 * 64 * 64];
// Pre-transposed offset+mod weights: [k][c][28]  (0..17 offset-out, 18..26 mod-out, 27 pad)
__device__ float g_wt2[9 * 64 * 28];

typedef unsigned long long ull;

__device__ __forceinline__ void ffma2(ull &acc, ull a, ull b) {
    asm("fma.rn.f32x2 %0, %1, %2, %0;" : "+l"(acc) : "l"(a), "l"(b));
}
__device__ __forceinline__ ull pack2(float x, float y) {
    ull r; asm("mov.b64 %0, {%1, %2};" : "=l"(r) : "f"(x), "f"(y)); return r;
}
__device__ __forceinline__ void unpack2(ull v, float &x, float &y) {
    asm("mov.b64 {%0, %1}, %2;" : "=f"(x), "=f"(y) : "l"(v));
}

// ---------------------------------------------------------------------------
// Prep: transpose weights once (trivial cost, coalesced writes).
// ---------------------------------------------------------------------------
__global__ void prep_kernel(const float* __restrict__ w,
                            const float* __restrict__ ow,
                            const float* __restrict__ mw)
{
    int i = blockIdx.x * 256 + threadIdx.x;
    if (i < 9 * 64 * 64) {
        int k = i >> 12;          // /4096
        int r = i & 4095;
        int c = r >> 6;
        int o = r & 63;
        g_wt[i] = w[o * 576 + c * 9 + k];
    }
    int j = i - 9 * 64 * 64;
    if (j >= 0 && j < 9 * 64 * 28) {
        int k = j / (64 * 28);
        int r = j % (64 * 28);
        int c = r / 28;
        int t = r % 28;
        float v = 0.f;
        if (t < 18)      v = ow[t * 576 + c * 9 + k];
        else if (t < 27) v = mw[(t - 18) * 576 + c * 9 + k];
        g_wt2[j] = v;
    }
}

// ---------------------------------------------------------------------------
// Kernel 1: fused offset-conv (18) + mod-conv (9) + 2*sigmoid.
// 1 thread per pixel, outer loop over taps, weights staged per-tap in smem,
// neighbor reads are coalesced global loads (L2-resident), FFMA2 accumulation.
// ---------------------------------------------------------------------------
__global__ __launch_bounds__(128, 8)
void offmask_kernel(const float* __restrict__ omap, const float* __restrict__ mmap,
                    const float* __restrict__ obias, const float* __restrict__ mbias)
{
    __shared__ float ws[64 * 28];    // 7 KB

    const int tid = threadIdx.x;
    const int b   = blockIdx.x >> 7;
    const int row = blockIdx.x & 127;
    const int wo  = tid;

    ull acc[14];
#pragma unroll
    for (int i = 0; i < 14; i++) acc[i] = 0ull;

    const float* ob = omap + (size_t)b * Cc * HW;
    const float* mb = mmap + (size_t)b * Cc * HW;

    for (int k = 0; k < 9; k++) {
        __syncthreads();
        for (int i = tid; i < 64 * 28; i += 128) ws[i] = g_wt2[k * 64 * 28 + i];
        __syncthreads();

        const int ki = k / 3, kj = k % 3;
        const int py = row - 1 + ki;
        const int px = wo - 1 + kj;
        const bool valid = ((unsigned)py < (unsigned)Hh) & ((unsigned)px < (unsigned)Ww);
        const float* qo = ob + py * Ww + px;
        const float* qm = mb + py * Ww + px;

#pragma unroll 4
        for (int c = 0; c < Cc; c++) {
            float iv = valid ? __ldg(qo + c * HW) : 0.f;
            float mv = valid ? __ldg(qm + c * HW) : 0.f;
            ull ai = pack2(iv, iv);
            ull am = pack2(mv, mv);
            const ulonglong2* wc = (const ulonglong2*)&ws[c * 28];
            ulonglong2 w;
            w = wc[0]; ffma2(acc[0],  ai, w.x); ffma2(acc[1],  ai, w.y);
            w = wc[1]; ffma2(acc[2],  ai, w.x); ffma2(acc[3],  ai, w.y);
            w = wc[2]; ffma2(acc[4],  ai, w.x); ffma2(acc[5],  ai, w.y);
            w = wc[3]; ffma2(acc[6],  ai, w.x); ffma2(acc[7],  ai, w.y);
            w = wc[4]; ffma2(acc[8],  ai, w.x); ffma2(acc[9],  am, w.y);
            w = wc[5]; ffma2(acc[10], am, w.x); ffma2(acc[11], am, w.y);
            w = wc[6]; ffma2(acc[12], am, w.x); ffma2(acc[13], am, w.y);
        }
    }

    // Epilogue: bias, sigmoid, write scratch
    float v[28];
#pragma unroll
    for (int i = 0; i < 14; i++) unpack2(acc[i], v[2 * i], v[2 * i + 1]);

    const int p = row * Ww + wo;
    float* S = g_scratch + (size_t)b * 27 * HW;
#pragma unroll
    for (int k = 0; k < 9; k++) {
        S[k * HW + p]       = v[2 * k]     + __ldg(&obias[2 * k]);
        S[(9 + k) * HW + p] = v[2 * k + 1] + __ldg(&obias[2 * k + 1]);
    }
#pragma unroll
    for (int t = 0; t < 9; t++) {
        float z = v[18 + t] + __ldg(&mbias[t]);
        S[(18 + t) * HW + p] = 2.0f / (1.0f + expf(-z));
    }
}

// ---------------------------------------------------------------------------
// Kernel 2: deformable conv GEMM.
// 1 thread per pixel, 64 out-ch as 32 packed f32x2 accumulators.
// Outer loop: tap k (descriptors computed ONCE: validity folded into 4
// combined corner weights, 4 clamped base pointers). Inner loop: channel c
// with immediate offsets (no per-iteration address ALU). FFMA2 GEMM.
// ---------------------------------------------------------------------------
__global__ __launch_bounds__(128, 4)
void deform_kernel(const float* __restrict__ x, float* __restrict__ out)
{
    __shared__ float ws[64 * 64];    // 16 KB, ws[c*64 + o]

    const int tid = threadIdx.x;
    const int b   = blockIdx.x >> 7;
    const int row = blockIdx.x & 127;
    const int wo  = tid;
    const int p   = row * Ww + wo;

    const float* S  = g_scratch + (size_t)b * 27 * HW;
    const float* xb = x + (size_t)b * Cc * HW;

    ull acc[32];
#pragma unroll
    for (int i = 0; i < 32; i++) acc[i] = 0ull;

    for (int k = 0; k < 9; k++) {
        __syncthreads();
        for (int i = tid; i < 64 * 64; i += 128) ws[i] = g_wt[k * 4096 + i];
        __syncthreads();

        const float dy = S[k * HW + p];
        const float dx = S[(9 + k) * HW + p];
        const float m  = S[(18 + k) * HW + p];
        const float py = dy + (float)(row - 1 + k / 3);
        const float px = dx + (float)(wo - 1 + k % 3);
        const float fy = floorf(py), fx = floorf(px);
        const int y0 = (int)fy, x0 = (int)fx;
        const int y1 = y0 + 1,  x1 = x0 + 1;
        const float wy = py - fy, wx = px - fx;

        const bool vy0 = ((unsigned)y0 < (unsigned)Hh);
        const bool vy1 = ((unsigned)y1 < (unsigned)Hh);
        const bool vx0 = ((unsigned)x0 < (unsigned)Ww);
        const bool vx1 = ((unsigned)x1 < (unsigned)Ww);
        const int y0c = min(max(y0, 0), Hh - 1);
        const int y1c = min(max(y1, 0), Hh - 1);
        const int x0c = min(max(x0, 0), Ww - 1);
        const int x1c = min(max(x1, 0), Ww - 1);

        // Combined corner weights (bilinear * mask * validity)
        float c00 = (1.f - wy) * (1.f - wx) * m; c00 = (vy0 & vx0) ? c00 : 0.f;
        float c01 = (1.f - wy) * wx         * m; c01 = (vy0 & vx1) ? c01 : 0.f;
        float c10 = wy * (1.f - wx)         * m; c10 = (vy1 & vx0) ? c10 : 0.f;
        float c11 = wy * wx                 * m; c11 = (vy1 & vx1) ? c11 : 0.f;

        const float* q00 = xb + y0c * Ww + x0c;
        const float* q01 = xb + y0c * Ww + x1c;
        const float* q10 = xb + y1c * Ww + x0c;
        const float* q11 = xb + y1c * Ww + x1c;

#pragma unroll 4
        for (int c = 0; c < Cc; c++) {
            float s = __ldg(q00 + c * HW) * c00;
            s = fmaf(__ldg(q01 + c * HW), c01, s);
            s = fmaf(__ldg(q10 + c * HW), c10, s);
            s = fmaf(__ldg(q11 + c * HW), c11, s);
            const ull s2 = pack2(s, s);
            const ulonglong2* wc = (const ulonglong2*)&ws[c * 64];
#pragma unroll
            for (int j = 0; j < 16; j++) {
                ulonglong2 w = wc[j];
                ffma2(acc[2 * j],     s2, w.x);
                ffma2(acc[2 * j + 1], s2, w.y);
            }
        }
    }

    // Write out: out[b][o][row][wo]
    float* op = out + (size_t)b * Oo * HW + p;
#pragma unroll
    for (int i = 0; i < 32; i++) {
        float lo, hi;
        unpack2(acc[i], lo, hi);
        op[(2 * i)     * HW] = lo;
        op[(2 * i + 1) * HW] = hi;
    }
}

// ---------------------------------------------------------------------------

extern "C" void kernel_launch(void* const* d_in, const int* in_sizes, int n_in,
                              void* d_out, int out_size)
{
    const float* x     = (const float*)d_in[0];
    const float* omap  = (const float*)d_in[1];
    const float* mmap  = (const float*)d_in[2];
    const float* ow    = (const float*)d_in[3];
    const float* obias = (const float*)d_in[4];
    const float* mw    = (const float*)d_in[5];
    const float* mbias = (const float*)d_in[6];
    const float* w     = (const float*)d_in[7];
    float* out = (float*)d_out;

    const int prep_total = 9 * 64 * 64 + 9 * 64 * 28;
    prep_kernel<<<(prep_total + 255) / 256, 256>>>(w, ow, mw);

    dim3 grid(Bb * Hh);     // 512 blocks, 1 output row each
    dim3 block(128);
    offmask_kernel<<<grid, block>>>(omap, mmap, obias, mbias);
    deform_kernel<<<grid, block>>>(x, out);
}

// round 4
// speedup vs baseline: 1.7295x; 1.2882x over previous
#include <cuda_runtime.h>
#include <math.h>
#include <stdint.h>

#define HW   (128 * 128)
#define Hh   128
#define Ww   128
#define Bb   4
#define Cc   64
#define Oo   64

// Scratch: offsets/mask planes [B][27][H][W]  (0..8 dy_k, 9..17 dx_k, 18..26 mask_k)
__device__ float g_scratch[Bb * 27 * HW];
// Pre-transposed offset+mod weights: [k][c][28]  (0..17 offset-out, 18..26 mod-out, 27 pad)
__device__ float g_wt2[9 * 64 * 28];
// Pre-split tf32 B matrices for main GEMM: [tap][o][c]  (o = out-ch row, c = K index)
__device__ float g_wbh[9 * 64 * 64];
__device__ float g_wbl[9 * 64 * 64];

typedef unsigned long long ull;

// ---------------- helpers ----------------
__device__ __forceinline__ uint32_t f2tf32(float s) {
    uint32_t r; asm("cvt.rna.tf32.f32 %0, %1;" : "=r"(r) : "f"(s)); return r;
}
__device__ __forceinline__ void ffma2(ull &acc, ull a, ull b) {
    asm("fma.rn.f32x2 %0, %1, %2, %0;" : "+l"(acc) : "l"(a), "l"(b));
}
__device__ __forceinline__ ull pack2(float x, float y) {
    ull r; asm("mov.b64 %0, {%1, %2};" : "=l"(r) : "f"(x), "f"(y)); return r;
}
__device__ __forceinline__ void unpack2(ull v, float &x, float &y) {
    asm("mov.b64 {%0, %1}, %2;" : "=f"(x), "=f"(y) : "l"(v));
}

#define MMA_TF32(d, a, b0, b1) \
    asm volatile("mma.sync.aligned.m16n8k8.row.col.f32.tf32.tf32.f32 " \
        "{%0,%1,%2,%3}, {%4,%5,%6,%7}, {%8,%9}, {%0,%1,%2,%3};" \
        : "+f"((d)[0]), "+f"((d)[1]), "+f"((d)[2]), "+f"((d)[3]) \
        : "r"((a)[0]), "r"((a)[1]), "r"((a)[2]), "r"((a)[3]), "r"(b0), "r"(b1))

// ---------------------------------------------------------------------------
// Prep: pre-transposed offmask weights + tf32-split main-GEMM B matrices.
// ---------------------------------------------------------------------------
__global__ void prep_kernel(const float* __restrict__ w,
                            const float* __restrict__ ow,
                            const float* __restrict__ mw)
{
    int i = blockIdx.x * 256 + threadIdx.x;
    if (i < 9 * 4096) {
        int k = i >> 12;      // tap
        int r = i & 4095;
        int o = r >> 6;       // out channel
        int c = r & 63;       // in channel (K index)
        float v = w[o * 576 + c * 9 + k];
        uint32_t hb = f2tf32(v);
        float hif = __uint_as_float(hb);
        g_wbh[i] = hif;
        g_wbl[i] = __uint_as_float(f2tf32(v - hif));
    }
    int j = i - 9 * 4096;
    if (j >= 0 && j < 9 * 64 * 28) {
        int k = j / (64 * 28);
        int r = j % (64 * 28);
        int c = r / 28;
        int t = r % 28;
        float v = 0.f;
        if (t < 18)      v = ow[t * 576 + c * 9 + k];
        else if (t < 27) v = mw[(t - 18) * 576 + c * 9 + k];
        g_wt2[j] = v;
    }
}

// ---------------------------------------------------------------------------
// Kernel 1: fused offset-conv (18) + mod-conv (9) + 2*sigmoid. (unchanged)
// ---------------------------------------------------------------------------
__global__ __launch_bounds__(128, 8)
void offmask_kernel(const float* __restrict__ omap, const float* __restrict__ mmap,
                    const float* __restrict__ obias, const float* __restrict__ mbias)
{
    __shared__ float ws[64 * 28];

    const int tid = threadIdx.x;
    const int b   = blockIdx.x >> 7;
    const int row = blockIdx.x & 127;
    const int wo  = tid;

    ull acc[14];
#pragma unroll
    for (int i = 0; i < 14; i++) acc[i] = 0ull;

    const float* ob = omap + (size_t)b * Cc * HW;
    const float* mb = mmap + (size_t)b * Cc * HW;

    for (int k = 0; k < 9; k++) {
        __syncthreads();
        for (int i = tid; i < 64 * 28; i += 128) ws[i] = g_wt2[k * 64 * 28 + i];
        __syncthreads();

        const int ki = k / 3, kj = k % 3;
        const int py = row - 1 + ki;
        const int px = wo - 1 + kj;
        const bool valid = ((unsigned)py < (unsigned)Hh) & ((unsigned)px < (unsigned)Ww);
        const float* qo = ob + py * Ww + px;
        const float* qm = mb + py * Ww + px;

#pragma unroll 4
        for (int c = 0; c < Cc; c++) {
            float iv = valid ? __ldg(qo + c * HW) : 0.f;
            float mv = valid ? __ldg(qm + c * HW) : 0.f;
            ull ai = pack2(iv, iv);
            ull am = pack2(mv, mv);
            const ulonglong2* wc = (const ulonglong2*)&ws[c * 28];
            ulonglong2 w;
            w = wc[0]; ffma2(acc[0],  ai, w.x); ffma2(acc[1],  ai, w.y);
            w = wc[1]; ffma2(acc[2],  ai, w.x); ffma2(acc[3],  ai, w.y);
            w = wc[2]; ffma2(acc[4],  ai, w.x); ffma2(acc[5],  ai, w.y);
            w = wc[3]; ffma2(acc[6],  ai, w.x); ffma2(acc[7],  ai, w.y);
            w = wc[4]; ffma2(acc[8],  ai, w.x); ffma2(acc[9],  am, w.y);
            w = wc[5]; ffma2(acc[10], am, w.x); ffma2(acc[11], am, w.y);
            w = wc[6]; ffma2(acc[12], am, w.x); ffma2(acc[13], am, w.y);
        }
    }

    float v[28];
#pragma unroll
    for (int i = 0; i < 14; i++) unpack2(acc[i], v[2 * i], v[2 * i + 1]);

    const int p = row * Ww + wo;
    float* S = g_scratch + (size_t)b * 27 * HW;
#pragma unroll
    for (int k = 0; k < 9; k++) {
        S[k * HW + p]       = v[2 * k]     + __ldg(&obias[2 * k]);
        S[(9 + k) * HW + p] = v[2 * k + 1] + __ldg(&obias[2 * k + 1]);
    }
#pragma unroll
    for (int t = 0; t < 9; t++) {
        float z = v[18 + t] + __ldg(&mbias[t]);
        S[(18 + t) * HW + p] = 2.0f / (1.0f + expf(-z));
    }
}

// ---------------------------------------------------------------------------
// Kernel 2: deformable conv as warp-level tf32 MMA implicit GEMM.
// CTA = 1 image row (M=128 pixels), N=64 outch, K=576 (9 taps x 64 ch).
// Per tap: each thread samples its pixel's 64 channels (bilinear gather),
// splits f32 -> tf32 hi + tf32 lo, stores to smem A[pix][ch] (stride 68,
// conflict-free). B (pre-split weights) staged to smem [o][ch] stride 68.
// Each warp computes rows [warp*32, warp*32+32): 2 m-tiles x 8 n-tiles of
// mma.sync.m16n8k8 tf32 with 3-product precision split; acc in registers.
// ---------------------------------------------------------------------------
#define SA_STRIDE 68
#define SA_HI 0
#define SA_LO (SA_HI + 128 * SA_STRIDE)          // 8704
#define SB_HI (SA_LO + 128 * SA_STRIDE)          // 17408
#define SB_LO (SB_HI + 64 * SA_STRIDE)           // 21760
#define SM_FLOATS (SB_LO + 64 * SA_STRIDE)       // 26112 floats = 104448 B

__global__ __launch_bounds__(128)
void deform_kernel(const float* __restrict__ x, float* __restrict__ out)
{
    extern __shared__ float smf[];
    uint32_t* smu = (uint32_t*)smf;

    const int tid  = threadIdx.x;
    const int lane = tid & 31;
    const int warp = tid >> 5;
    const int g    = lane >> 2;      // group id 0..7
    const int tg   = lane & 3;       // thread-in-group 0..3

    const int b   = blockIdx.x >> 7;
    const int row = blockIdx.x & 127;
    const int wo  = tid;             // pixel x = M row index
    const int p   = row * Ww + wo;

    const float* S  = g_scratch + (size_t)b * 27 * HW;
    const float* xb = x + (size_t)b * Cc * HW;

    float acc[2][8][4];
#pragma unroll
    for (int mt = 0; mt < 2; mt++)
#pragma unroll
        for (int nt = 0; nt < 8; nt++)
#pragma unroll
            for (int r = 0; r < 4; r++) acc[mt][nt][r] = 0.f;

#pragma unroll 1
    for (int k = 0; k < 9; k++) {
        __syncthreads();   // previous tap's fragment reads complete

        // ---- stage B tiles: [o][c] stride 68, from [tap][o][c] global ----
        {
            const float4* sh = (const float4*)&g_wbh[k * 4096];
            const float4* sl = (const float4*)&g_wbl[k * 4096];
#pragma unroll
            for (int i = tid; i < 1024; i += 128) {
                int o = i >> 4, q = i & 15;
                float4 vh = sh[o * 16 + q];
                float4 vl = sl[o * 16 + q];
                *(float4*)&smf[SB_HI + o * SA_STRIDE + q * 4] = vh;
                *(float4*)&smf[SB_LO + o * SA_STRIDE + q * 4] = vl;
            }
        }

        // ---- tap descriptor ----
        const float dy = S[k * HW + p];
        const float dx = S[(9 + k) * HW + p];
        const float m  = S[(18 + k) * HW + p];
        const float py = dy + (float)(row - 1 + k / 3);
        const float px = dx + (float)(wo - 1 + k % 3);
        const float fy = floorf(py), fx = floorf(px);
        const int y0 = (int)fy, x0 = (int)fx;
        const int y1 = y0 + 1,  x1 = x0 + 1;
        const float wy = py - fy, wx = px - fx;

        const bool vy0 = ((unsigned)y0 < (unsigned)Hh);
        const bool vy1 = ((unsigned)y1 < (unsigned)Hh);
        const bool vx0 = ((unsigned)x0 < (unsigned)Ww);
        const bool vx1 = ((unsigned)x1 < (unsigned)Ww);
        const int y0c = min(max(y0, 0), Hh - 1);
        const int y1c = min(max(y1, 0), Hh - 1);
        const int x0c = min(max(x0, 0), Ww - 1);
        const int x1c = min(max(x1, 0), Ww - 1);

        float c00 = (1.f - wy) * (1.f - wx) * m; c00 = (vy0 & vx0) ? c00 : 0.f;
        float c01 = (1.f - wy) * wx         * m; c01 = (vy0 & vx1) ? c01 : 0.f;
        float c10 = wy * (1.f - wx)         * m; c10 = (vy1 & vx0) ? c10 : 0.f;
        float c11 = wy * wx                 * m; c11 = (vy1 & vx1) ? c11 : 0.f;

        const float* q00 = xb + y0c * Ww + x0c;
        const float* q01 = xb + y0c * Ww + x1c;
        const float* q10 = xb + y1c * Ww + x0c;
        const float* q11 = xb + y1c * Ww + x1c;

        // ---- sample 64 channels, split hi/lo, STS into A tiles ----
#pragma unroll 4
        for (int cg = 0; cg < 16; cg++) {
            float hi4[4], lo4[4];
#pragma unroll
            for (int j = 0; j < 4; j++) {
                const int c = cg * 4 + j;
                float s = __ldg(q00 + c * HW) * c00;
                s = fmaf(__ldg(q01 + c * HW), c01, s);
                s = fmaf(__ldg(q10 + c * HW), c10, s);
                s = fmaf(__ldg(q11 + c * HW), c11, s);
                uint32_t hb = f2tf32(s);
                hi4[j] = __uint_as_float(hb);
                lo4[j] = __uint_as_float(f2tf32(s - hi4[j]));
            }
            *(float4*)&smf[SA_HI + wo * SA_STRIDE + cg * 4] =
                make_float4(hi4[0], hi4[1], hi4[2], hi4[3]);
            *(float4*)&smf[SA_LO + wo * SA_STRIDE + cg * 4] =
                make_float4(lo4[0], lo4[1], lo4[2], lo4[3]);
        }

        __syncthreads();

        // ---- GEMM: 8 k-steps x (2 m-tiles x 8 n-tiles) x 3 split products ----
#pragma unroll
        for (int ks = 0; ks < 8; ks++) {
            uint32_t ah[2][4], al[2][4];
#pragma unroll
            for (int mt = 0; mt < 2; mt++) {
                const int r0 = warp * 32 + mt * 16 + g;
                const int base = r0 * SA_STRIDE + ks * 8 + tg;
                ah[mt][0] = smu[SA_HI + base];
                ah[mt][1] = smu[SA_HI + base + 8 * SA_STRIDE];
                ah[mt][2] = smu[SA_HI + base + 4];
                ah[mt][3] = smu[SA_HI + base + 8 * SA_STRIDE + 4];
                al[mt][0] = smu[SA_LO + base];
                al[mt][1] = smu[SA_LO + base + 8 * SA_STRIDE];
                al[mt][2] = smu[SA_LO + base + 4];
                al[mt][3] = smu[SA_LO + base + 8 * SA_STRIDE + 4];
            }
#pragma unroll
            for (int nt = 0; nt < 8; nt++) {
                const int o  = nt * 8 + g;
                const int bb = o * SA_STRIDE + ks * 8 + tg;
                uint32_t bh0 = smu[SB_HI + bb], bh1 = smu[SB_HI + bb + 4];
                uint32_t bl0 = smu[SB_LO + bb], bl1 = smu[SB_LO + bb + 4];
#pragma unroll
                for (int mt = 0; mt < 2; mt++) {
                    MMA_TF32(acc[mt][nt], ah[mt], bh0, bh1);
                    MMA_TF32(acc[mt][nt], al[mt], bh0, bh1);
                    MMA_TF32(acc[mt][nt], ah[mt], bl0, bl1);
                }
            }
        }
    }

    // ---- epilogue: write D fragments to out[b][o][row][x] ----
    float* ob = out + (size_t)b * Oo * HW + row * Ww;
#pragma unroll
    for (int mt = 0; mt < 2; mt++) {
        const int r0 = warp * 32 + mt * 16 + g;   // pixel x for c0,c1
        const int r1 = r0 + 8;                    // pixel x for c2,c3
#pragma unroll
        for (int nt = 0; nt < 8; nt++) {
            const int o0 = nt * 8 + tg * 2;
            ob[(o0)     * HW + r0] = acc[mt][nt][0];
            ob[(o0 + 1) * HW + r0] = acc[mt][nt][1];
            ob[(o0)     * HW + r1] = acc[mt][nt][2];
            ob[(o0 + 1) * HW + r1] = acc[mt][nt][3];
        }
    }
}

// ---------------------------------------------------------------------------

extern "C" void kernel_launch(void* const* d_in, const int* in_sizes, int n_in,
                              void* d_out, int out_size)
{
    const float* x     = (const float*)d_in[0];
    const float* omap  = (const float*)d_in[1];
    const float* mmap  = (const float*)d_in[2];
    const float* ow    = (const float*)d_in[3];
    const float* obias = (const float*)d_in[4];
    const float* mw    = (const float*)d_in[5];
    const float* mbias = (const float*)d_in[6];
    const float* w     = (const float*)d_in[7];
    float* out = (float*)d_out;

    const int prep_total = 9 * 4096 + 9 * 64 * 28;
    prep_kernel<<<(prep_total + 255) / 256, 256>>>(w, ow, mw);

    dim3 grid(Bb * Hh);     // 512 blocks, 1 image row each
    dim3 block(128);
    offmask_kernel<<<grid, block>>>(omap, mmap, obias, mbias);

    const int smem_bytes = SM_FLOATS * (int)sizeof(float);   // 104448
    cudaFuncSetAttribute(deform_kernel, cudaFuncAttributeMaxDynamicSharedMemorySize, smem_bytes);
    deform_kernel<<<grid, block, smem_bytes>>>(x, out);
}